// round 3
// baseline (speedup 1.0000x reference)
#include <cuda_runtime.h>

#define Bn 64
#define Nn 4096
#define Kk 11
#define Dd 192
#define HIDn 128
#define EPSF 1e-8f
#define LN_EPSF 1e-5f
#define SCALEF 0.07216878364870323f

__device__ float g_mu[Bn * Nn];
__device__ float g_rstd[Bn * Nn];
__device__ float g_slots[Bn * Kk * Dd];
__device__ float g_qt[Bn * Kk * Dd];
__device__ float g_c[Bn * Kk];
__device__ float g_U[Bn * Kk * Dd];
__device__ float g_S[Bn * Kk];
__device__ float g_WihT[Dd * 3 * Dd];
__device__ float g_WhhT[Dd * 3 * Dd];

__global__ void k_init(const float* __restrict__ noise, const float* __restrict__ smu,
                       const float* __restrict__ ssig, const float* __restrict__ Wih,
                       const float* __restrict__ Whh) {
    const int T0 = Bn * Kk * Dd, T1 = T0 + 3 * Dd * Dd, T2 = T1 + 3 * Dd * Dd;
    for (int i = blockIdx.x * blockDim.x + threadIdx.x; i < T2; i += gridDim.x * blockDim.x) {
        if (i < T0) { int d = i % Dd; g_slots[i] = smu[d] + ssig[d] * noise[i]; }
        else if (i < T1) { int i2 = i - T0; g_WihT[(i2 % Dd) * (3 * Dd) + i2 / Dd] = Wih[i2]; }
        else { int i2 = i - T1; g_WhhT[(i2 % Dd) * (3 * Dd) + i2 / Dd] = Whh[i2]; }
    }
}

__global__ void k_stats(const float* __restrict__ x) {
    int wid = threadIdx.x >> 5, lane = threadIdx.x & 31;
    int token = blockIdx.x * 8 + wid;
    const float* xp = x + (size_t)token * Dd;
    float v[6], s = 0.f;
#pragma unroll
    for (int i = 0; i < 6; i++) { v[i] = xp[lane + 32 * i]; s += v[i]; }
#pragma unroll
    for (int o = 16; o; o >>= 1) s += __shfl_xor_sync(~0u, s, o);
    float mu = s * (1.0f / Dd), q = 0.f;
#pragma unroll
    for (int i = 0; i < 6; i++) { float d = v[i] - mu; q += d * d; }
#pragma unroll
    for (int o = 16; o; o >>= 1) q += __shfl_xor_sync(~0u, q, o);
    if (lane == 0) { g_mu[token] = mu; g_rstd[token] = rsqrtf(q * (1.0f / Dd) + LN_EPSF); }
}

__global__ __launch_bounds__(192) void k_pre(const float* __restrict__ Wq,
                                             const float* __restrict__ bq,
                                             const float* __restrict__ Wk,
                                             const float* __restrict__ bk,
                                             const float* __restrict__ lnw,
                                             const float* __restrict__ lnb) {
    __shared__ float sn[Kk][Dd], qs[Kk][Dd], red[6], bmu[Kk], brs[Kk];
    int b = blockIdx.x, t = threadIdx.x, wid = t >> 5, lane = t & 31;
    float v[Kk];
#pragma unroll
    for (int r = 0; r < Kk; r++) v[r] = g_slots[(b * Kk + r) * Dd + t];
#pragma unroll 1
    for (int r = 0; r < Kk; r++) {
        float s = v[r];
#pragma unroll
        for (int o = 16; o; o >>= 1) s += __shfl_xor_sync(~0u, s, o);
        if (lane == 0) red[wid] = s;
        __syncthreads();
        if (t == 0) { float tt = 0.f; for (int w = 0; w < 6; w++) tt += red[w]; bmu[r] = tt * (1.0f / Dd); }
        __syncthreads();
        float d = v[r] - bmu[r], q2 = d * d;
#pragma unroll
        for (int o = 16; o; o >>= 1) q2 += __shfl_xor_sync(~0u, q2, o);
        if (lane == 0) red[wid] = q2;
        __syncthreads();
        if (t == 0) { float tt = 0.f; for (int w = 0; w < 6; w++) tt += red[w]; brs[r] = rsqrtf(tt * (1.0f / Dd) + LN_EPSF); }
        __syncthreads();
        sn[r][t] = (v[r] - bmu[r]) * brs[r] * lnw[t] + lnb[t];
        __syncthreads();
    }
    float qa[Kk];
#pragma unroll
    for (int r = 0; r < Kk; r++) qa[r] = 0.f;
    for (int e = 0; e < Dd; e++) {
        float w = Wq[e * Dd + t];
#pragma unroll
        for (int r = 0; r < Kk; r++) qa[r] = fmaf(sn[r][e], w, qa[r]);
    }
    float bqv = bq[t];
#pragma unroll
    for (int r = 0; r < Kk; r++) qs[r][t] = qa[r] + bqv;
    __syncthreads();
    float qt[Kk];
#pragma unroll
    for (int r = 0; r < Kk; r++) qt[r] = 0.f;
    for (int d2 = 0; d2 < Dd; d2++) {
        float w = Wk[t * Dd + d2];
#pragma unroll
        for (int r = 0; r < Kk; r++) qt[r] = fmaf(w, qs[r][d2], qt[r]);
    }
#pragma unroll
    for (int r = 0; r < Kk; r++) g_qt[(b * Kk + r) * Dd + t] = qt[r] * SCALEF;
#pragma unroll 1
    for (int r = 0; r < Kk; r++) {
        float p = qs[r][t] * bk[t];
#pragma unroll
        for (int o = 16; o; o >>= 1) p += __shfl_xor_sync(~0u, p, o);
        if (lane == 0) red[wid] = p;
        __syncthreads();
        if (t == 0) { float tt = 0.f; for (int w = 0; w < 6; w++) tt += red[w]; g_c[b * Kk + r] = tt * SCALEF; }
        __syncthreads();
    }
#pragma unroll
    for (int r = 0; r < Kk; r++) g_U[(b * Kk + r) * Dd + t] = 0.f;
    if (t < Kk) g_S[b * Kk + t] = 0.f;
}

__global__ __launch_bounds__(256, 1) void k_attn(const float* __restrict__ x,
                                                 const float* __restrict__ lnw,
                                                 const float* __restrict__ lnb,
                                                 float* __restrict__ attn_out, int wr) {
    int b = blockIdx.y, wid = threadIdx.x >> 5, lane = threadIdx.x & 31;
    int n0 = (blockIdx.x * 8 + wid) * 32;
    float qtr[Kk][6], cr[Kk], lw[6], lb[6];
#pragma unroll
    for (int k = 0; k < Kk; k++) {
        cr[k] = g_c[b * Kk + k];
#pragma unroll
        for (int i = 0; i < 6; i++) qtr[k][i] = g_qt[(b * Kk + k) * Dd + lane + 32 * i];
    }
#pragma unroll
    for (int i = 0; i < 6; i++) { lw[i] = lnw[lane + 32 * i]; lb[i] = lnb[lane + 32 * i]; }
    float Ua[Kk][6], Sa[Kk];
#pragma unroll
    for (int k = 0; k < Kk; k++) {
        Sa[k] = 0.f;
#pragma unroll
        for (int i = 0; i < 6; i++) Ua[k][i] = 0.f;
    }
    const float* xb = x + (size_t)b * Nn * Dd;
#pragma unroll 1
    for (int t = 0; t < 32; t++) {
        int n = n0 + t;
        float mu = g_mu[b * Nn + n], rs = g_rstd[b * Nn + n];
        const float* xp = xb + (size_t)n * Dd;
        float xn[6];
#pragma unroll
        for (int i = 0; i < 6; i++) xn[i] = (__ldg(&xp[lane + 32 * i]) - mu) * rs * lw[i] + lb[i];
        float dk[Kk];
#pragma unroll
        for (int k = 0; k < Kk; k++) {
            float s = 0.f;
#pragma unroll
            for (int i = 0; i < 6; i++) s = fmaf(xn[i], qtr[k][i], s);
            dk[k] = s;
        }
#pragma unroll
        for (int o = 16; o; o >>= 1)
#pragma unroll
            for (int k = 0; k < Kk; k++) dk[k] += __shfl_xor_sync(~0u, dk[k], o);
        float mx = dk[0] + cr[0];
#pragma unroll
        for (int k = 0; k < Kk; k++) { dk[k] += cr[k]; mx = fmaxf(mx, dk[k]); }
        float sum = 0.f;
#pragma unroll
        for (int k = 0; k < Kk; k++) { dk[k] = __expf(dk[k] - mx); sum += dk[k]; }
        float inv = __fdividef(1.0f, sum);
#pragma unroll
        for (int k = 0; k < Kk; k++) {
            dk[k] = fmaf(dk[k], inv, EPSF);
            Sa[k] += dk[k];
#pragma unroll
            for (int i = 0; i < 6; i++) Ua[k][i] = fmaf(dk[k], xn[i], Ua[k][i]);
        }
        if (wr) {
            float av = dk[0];
#pragma unroll
            for (int k = 1; k < Kk; k++) if (lane == k) av = dk[k];
            if (lane < Kk) attn_out[((size_t)b * Kk + lane) * Nn + n] = av;
        }
    }
#pragma unroll
    for (int k = 0; k < Kk; k++)
#pragma unroll
        for (int i = 0; i < 6; i++)
            atomicAdd(&g_U[(b * Kk + k) * Dd + lane + 32 * i], Ua[k][i]);
    if (lane == 0)
#pragma unroll
        for (int k = 0; k < Kk; k++) atomicAdd(&g_S[b * Kk + k], Sa[k]);
}

__global__ __launch_bounds__(192, 1) void k_upd(
    const float* __restrict__ Wv, const float* __restrict__ bv,
    const float* __restrict__ bih, const float* __restrict__ bhh,
    const float* __restrict__ lnw, const float* __restrict__ lnb,
    const float* __restrict__ W1, const float* __restrict__ b1,
    const float* __restrict__ W2, const float* __restrict__ b2,
    float* __restrict__ slots_out, int last) {
    __shared__ float A[Kk][Dd], Bf[Kk][Dd], C[Kk][Dd], M1[Kk][HIDn];
    __shared__ float redA[Kk][6], redB[Kk][6], bmu2[Kk], brs2[Kk], binv[Kk];
    int b = blockIdx.x, t = threadIdx.x, wid = t >> 5, lane = t & 31;
    if (t < Kk) binv[t] = __fdividef(1.0f, g_S[b * Kk + t]);
    __syncthreads();
#pragma unroll
    for (int r = 0; r < Kk; r++) {
        A[r][t] = g_U[(b * Kk + r) * Dd + t] * binv[r];
        C[r][t] = g_slots[(b * Kk + r) * Dd + t];
    }
    __syncthreads();
    {
        float acc[Kk];
#pragma unroll
        for (int r = 0; r < Kk; r++) acc[r] = 0.f;
        for (int e = 0; e < Dd; e++) {
            float w = Wv[e * Dd + t];
#pragma unroll
            for (int r = 0; r < Kk; r++) acc[r] = fmaf(A[r][e], w, acc[r]);
        }
        float bb = bv[t];
        __syncthreads();
#pragma unroll
        for (int r = 0; r < Kk; r++) Bf[r][t] = acc[r] + bb;
    }
    __syncthreads();
    {
        float ax0[Kk], ax1[Kk], ax2[Kk], ah0[Kk], ah1[Kk], ah2[Kk];
#pragma unroll
        for (int r = 0; r < Kk; r++) { ax0[r] = ax1[r] = ax2[r] = 0.f; ah0[r] = ah1[r] = ah2[r] = 0.f; }
        for (int e = 0; e < Dd; e++) {
            float w0 = g_WihT[e * (3 * Dd) + t];
            float w1 = g_WihT[e * (3 * Dd) + Dd + t];
            float w2 = g_WihT[e * (3 * Dd) + 2 * Dd + t];
            float v0 = g_WhhT[e * (3 * Dd) + t];
            float v1 = g_WhhT[e * (3 * Dd) + Dd + t];
            float v2 = g_WhhT[e * (3 * Dd) + 2 * Dd + t];
#pragma unroll
            for (int r = 0; r < Kk; r++) {
                float u = Bf[r][e], s = C[r][e];
                ax0[r] = fmaf(u, w0, ax0[r]); ax1[r] = fmaf(u, w1, ax1[r]); ax2[r] = fmaf(u, w2, ax2[r]);
                ah0[r] = fmaf(s, v0, ah0[r]); ah1[r] = fmaf(s, v1, ah1[r]); ah2[r] = fmaf(s, v2, ah2[r]);
            }
        }
        float bir = bih[t], biz = bih[Dd + t], bin_ = bih[2 * Dd + t];
        float bhr = bhh[t], bhz = bhh[Dd + t], bhn = bhh[2 * Dd + t];
#pragma unroll
        for (int r = 0; r < Kk; r++) {
            float rg = 1.0f / (1.0f + __expf(-(ax0[r] + bir + ah0[r] + bhr)));
            float zg = 1.0f / (1.0f + __expf(-(ax1[r] + biz + ah1[r] + bhz)));
            float ng = tanhf(fmaf(rg, ah2[r] + bhn, ax2[r] + bin_));
            A[r][t] = (1.0f - zg) * ng + zg * C[r][t];
        }
    }
    __syncthreads();
    {
        float vv[Kk];
#pragma unroll
        for (int r = 0; r < Kk; r++) {
            float v = A[r][t];
            vv[r] = v;
            float s1 = v, s2 = v * v;
#pragma unroll
            for (int o = 16; o; o >>= 1) {
                s1 += __shfl_xor_sync(~0u, s1, o);
                s2 += __shfl_xor_sync(~0u, s2, o);
            }
            if (lane == 0) { redA[r][wid] = s1; redB[r][wid] = s2; }
        }
        __syncthreads();
        if (t < Kk) {
            float s1 = 0.f, s2 = 0.f;
            for (int w = 0; w < 6; w++) { s1 += redA[t][w]; s2 += redB[t][w]; }
            float mu = s1 * (1.0f / Dd);
            bmu2[t] = mu;
            brs2[t] = rsqrtf(s2 * (1.0f / Dd) - mu * mu + LN_EPSF);
        }
        __syncthreads();
#pragma unroll
        for (int r = 0; r < Kk; r++) Bf[r][t] = (vv[r] - bmu2[r]) * brs2[r] * lnw[t] + lnb[t];
    }
    __syncthreads();
    if (t < HIDn) {
        float acc[Kk];
#pragma unroll
        for (int r = 0; r < Kk; r++) acc[r] = 0.f;
        for (int e = 0; e < Dd; e++) {
            float w = W1[e * HIDn + t];
#pragma unroll
            for (int r = 0; r < Kk; r++) acc[r] = fmaf(Bf[r][e], w, acc[r]);
        }
        float bb = b1[t];
#pragma unroll
        for (int r = 0; r < Kk; r++) M1[r][t] = fmaxf(acc[r] + bb, 0.0f);
    }
    __syncthreads();
    {
        float acc[Kk];
#pragma unroll
        for (int r = 0; r < Kk; r++) acc[r] = 0.f;
        for (int h = 0; h < HIDn; h++) {
            float w = W2[h * Dd + t];
#pragma unroll
            for (int r = 0; r < Kk; r++) acc[r] = fmaf(M1[r][h], w, acc[r]);
        }
        float bb = b2[t];
#pragma unroll
        for (int r = 0; r < Kk; r++) {
            float s = A[r][t] + acc[r] + bb;
            g_slots[(b * Kk + r) * Dd + t] = s;
            if (last) slots_out[(b * Kk + r) * Dd + t] = s;
        }
    }
}

extern "C" void kernel_launch(void* const* d_in, const int* in_sizes, int n_in,
                              void* d_out, int out_size) {
    const float* inputs = (const float*)d_in[0];
    const float* noise = (const float*)d_in[1];
    const float* smu = (const float*)d_in[2];
    const float* ssig = (const float*)d_in[3];
    const float* ln_in_w = (const float*)d_in[4];
    const float* ln_in_b = (const float*)d_in[5];
    const float* ln_sl_w = (const float*)d_in[6];
    const float* ln_sl_b = (const float*)d_in[7];
    const float* ln_ml_w = (const float*)d_in[8];
    const float* ln_ml_b = (const float*)d_in[9];
    const float* Wq = (const float*)d_in[10];
    const float* bq = (const float*)d_in[11];
    const float* Wk = (const float*)d_in[12];
    const float* bk = (const float*)d_in[13];
    const float* Wv = (const float*)d_in[14];
    const float* bv = (const float*)d_in[15];
    const float* Wih = (const float*)d_in[16];
    const float* Whh = (const float*)d_in[17];
    const float* bih = (const float*)d_in[18];
    const float* bhh = (const float*)d_in[19];
    const float* W1 = (const float*)d_in[20];
    const float* b1 = (const float*)d_in[21];
    const float* W2 = (const float*)d_in[22];
    const float* b2 = (const float*)d_in[23];

    float* out = (float*)d_out;
    float* slots_out = out;                       // [B, K, D]
    float* attn_out = out + Bn * Kk * Dd;         // [B, K, N]

    k_init<<<256, 256>>>(noise, smu, ssig, Wih, Whh);
    k_stats<<<(Bn * Nn) / 8, 256>>>(inputs);
    for (int it = 0; it < 3; it++) {
        k_pre<<<Bn, 192>>>(Wq, bq, Wk, bk, ln_sl_w, ln_sl_b);
        k_attn<<<dim3(16, Bn), 256>>>(inputs, ln_in_w, ln_in_b, attn_out, it == 2 ? 1 : 0);
        k_upd<<<Bn, 192>>>(Wv, bv, bih, bhh, ln_ml_w, ln_ml_b, W1, b1, W2, b2,
                           slots_out, it == 2 ? 1 : 0);
    }
}

// round 4
// speedup vs baseline: 1.0246x; 1.0246x over previous
#include <cuda_runtime.h>

#define Bn 64
#define Nn 4096
#define Kk 11
#define KP 12
#define Dd 192
#define HIDn 128
#define Tt 128
#define EPSF 1e-8f
#define LN_EPSF 1e-5f
#define SCALEF 0.07216878364870323f

__device__ float g_mu[Bn * Nn];
__device__ float g_rstd[Bn * Nn];
__device__ float g_slots[Bn * Kk * Dd];
__device__ float g_h[Bn * Kk * Dd];
__device__ float g_w2t[Bn * Dd * KP];
__device__ float g_w2sum[Bn * Kk];
__device__ float g_cc[Bn * Kk];
__device__ float g_R[Bn * Kk * Dd];
__device__ float g_s1[Bn * Kk];
__device__ float g_s2[Bn * Kk];
__device__ float g_WihT[Dd * 3 * Dd];
__device__ float g_WhhT[Dd * 3 * Dd];
__device__ float g_WkT[Dd * Dd];

// ---------------- init: slots, transpose Wih/Whh/Wk ----------------
__global__ void k_init(const float* __restrict__ noise, const float* __restrict__ smu,
                       const float* __restrict__ ssig, const float* __restrict__ Wih,
                       const float* __restrict__ Whh, const float* __restrict__ Wk) {
    const int T0 = Bn * Kk * Dd;
    const int T1 = T0 + 3 * Dd * Dd;
    const int T2 = T1 + 3 * Dd * Dd;
    const int T3 = T2 + Dd * Dd;
    for (int i = blockIdx.x * blockDim.x + threadIdx.x; i < T3; i += gridDim.x * blockDim.x) {
        if (i < T0) { int d = i % Dd; g_slots[i] = smu[d] + ssig[d] * noise[i]; }
        else if (i < T1) { int i2 = i - T0; g_WihT[(i2 % Dd) * (3 * Dd) + i2 / Dd] = Wih[i2]; }
        else if (i < T2) { int i2 = i - T1; g_WhhT[(i2 % Dd) * (3 * Dd) + i2 / Dd] = Whh[i2]; }
        else { int i2 = i - T2; g_WkT[(i2 % Dd) * Dd + i2 / Dd] = Wk[i2]; }
    }
}

// ---------------- per-token LN stats ----------------
__global__ void k_stats(const float* __restrict__ x) {
    int wid = threadIdx.x >> 5, lane = threadIdx.x & 31;
    int token = blockIdx.x * 8 + wid;
    const float* xp = x + (size_t)token * Dd;
    float v[6], s = 0.f;
#pragma unroll
    for (int i = 0; i < 6; i++) { v[i] = xp[lane + 32 * i]; s += v[i]; }
#pragma unroll
    for (int o = 16; o; o >>= 1) s += __shfl_xor_sync(~0u, s, o);
    float mu = s * (1.0f / Dd), q = 0.f;
#pragma unroll
    for (int i = 0; i < 6; i++) { float d = v[i] - mu; q += d * d; }
#pragma unroll
    for (int o = 16; o; o >>= 1) q += __shfl_xor_sync(~0u, q, o);
    if (lane == 0) { g_mu[token] = mu; g_rstd[token] = rsqrtf(q * (1.0f / Dd) + LN_EPSF); }
}

// ---------------- per-iter slot preprocessing ----------------
__global__ __launch_bounds__(192) void k_pre(const float* __restrict__ lnw_s,
                                             const float* __restrict__ lnb_s,
                                             const float* __restrict__ Wq,
                                             const float* __restrict__ bq,
                                             const float* __restrict__ bk,
                                             const float* __restrict__ lnw_in,
                                             const float* __restrict__ lnb_in) {
    __shared__ float snt[Dd * KP];
    __shared__ float qT[Dd * KP];
    __shared__ float red[24];
    int b = blockIdx.x, t = threadIdx.x, wid = t >> 5, lane = t & 31;
    if (t < 24) red[t] = 0.f;

    // LN of slots: warp-per-slot, no block barriers inside
    for (int r = wid; r < Kk; r += 6) {
        float v[6], s = 0.f;
#pragma unroll
        for (int i = 0; i < 6; i++) { v[i] = g_slots[(b * Kk + r) * Dd + lane + 32 * i]; s += v[i]; }
#pragma unroll
        for (int o = 16; o; o >>= 1) s += __shfl_xor_sync(~0u, s, o);
        float mu = s * (1.0f / Dd), q = 0.f;
#pragma unroll
        for (int i = 0; i < 6; i++) { float d = v[i] - mu; q += d * d; }
#pragma unroll
        for (int o = 16; o; o >>= 1) q += __shfl_xor_sync(~0u, q, o);
        float rstd = rsqrtf(q * (1.0f / Dd) + LN_EPSF);
#pragma unroll
        for (int i = 0; i < 6; i++) {
            int d = lane + 32 * i;
            snt[d * KP + r] = (v[i] - mu) * rstd * lnw_s[d] + lnb_s[d];
        }
    }
    __syncthreads();

    // q[r][t] = sn[r] . Wq[:,t] + bq[t]
    float qa[Kk];
#pragma unroll
    for (int r = 0; r < Kk; r++) qa[r] = 0.f;
    for (int e = 0; e < Dd; e++) {
        float4 s0 = *(const float4*)&snt[e * KP];
        float4 s1 = *(const float4*)&snt[e * KP + 4];
        float4 s2 = *(const float4*)&snt[e * KP + 8];
        float w = Wq[e * Dd + t];
        qa[0] = fmaf(s0.x, w, qa[0]); qa[1] = fmaf(s0.y, w, qa[1]);
        qa[2] = fmaf(s0.z, w, qa[2]); qa[3] = fmaf(s0.w, w, qa[3]);
        qa[4] = fmaf(s1.x, w, qa[4]); qa[5] = fmaf(s1.y, w, qa[5]);
        qa[6] = fmaf(s1.z, w, qa[6]); qa[7] = fmaf(s1.w, w, qa[7]);
        qa[8] = fmaf(s2.x, w, qa[8]); qa[9] = fmaf(s2.y, w, qa[9]);
        qa[10] = fmaf(s2.z, w, qa[10]);
    }
    float bqv = bq[t];
#pragma unroll
    for (int r = 0; r < Kk; r++) { qa[r] += bqv; qT[t * KP + r] = qa[r]; }
    __syncthreads();

    // qt[r][t] = sum_d WkT[d][t] * q[r][d]   (= row t of Wk dot q)
    float qt[Kk];
#pragma unroll
    for (int r = 0; r < Kk; r++) qt[r] = 0.f;
    for (int d = 0; d < Dd; d++) {
        float4 q0 = *(const float4*)&qT[d * KP];
        float4 q1 = *(const float4*)&qT[d * KP + 4];
        float4 q2 = *(const float4*)&qT[d * KP + 8];
        float w = g_WkT[d * Dd + t];
        qt[0] = fmaf(q0.x, w, qt[0]); qt[1] = fmaf(q0.y, w, qt[1]);
        qt[2] = fmaf(q0.z, w, qt[2]); qt[3] = fmaf(q0.w, w, qt[3]);
        qt[4] = fmaf(q1.x, w, qt[4]); qt[5] = fmaf(q1.y, w, qt[5]);
        qt[6] = fmaf(q1.z, w, qt[6]); qt[7] = fmaf(q1.w, w, qt[7]);
        qt[8] = fmaf(q2.x, w, qt[8]); qt[9] = fmaf(q2.y, w, qt[9]);
        qt[10] = fmaf(q2.z, w, qt[10]);
    }
    float lwv = lnw_in[t], lbv = lnb_in[t], bkv = bk[t];
    float ws[Kk], cp[Kk];
#pragma unroll
    for (int r = 0; r < Kk; r++) {
        float w2 = qt[r] * SCALEF * lwv;
        g_w2t[(b * Dd + t) * KP + r] = w2;
        ws[r] = w2;
        cp[r] = (lbv * qt[r] + qa[r] * bkv) * SCALEF;
    }
    g_w2t[(b * Dd + t) * KP + 11] = 0.f;
#pragma unroll
    for (int r = 0; r < Kk; r++) {
        float a = ws[r], c = cp[r];
#pragma unroll
        for (int o = 16; o; o >>= 1) {
            a += __shfl_xor_sync(~0u, a, o);
            c += __shfl_xor_sync(~0u, c, o);
        }
        if (lane == 0) { atomicAdd(&red[r], a); atomicAdd(&red[12 + r], c); }
    }
    __syncthreads();
    if (t < Kk) {
        g_w2sum[b * Kk + t] = red[t];
        g_cc[b * Kk + t] = red[12 + t];
        g_s1[b * Kk + t] = 0.f;
        g_s2[b * Kk + t] = 0.f;
    }
    for (int i = t; i < Kk * Dd; i += 192) g_R[b * Kk * Dd + i] = 0.f;
}

// ---------------- attention pass: token-per-thread, shuffle-free ----------------
__global__ __launch_bounds__(128) void k_attn(const float* __restrict__ x,
                                              float* __restrict__ attn_out, int wr) {
    extern __shared__ float sm[];
    float* Xs = sm;                 // Tt rows, stride 193
    float* A1 = sm + Tt * 193;      // Tt x KP  (a * rs)
    int b = blockIdx.y, tid = threadIdx.x, lane = tid & 31;
    int n0 = blockIdx.x * Tt;

    // phase A: load raw x tile
    const float* xb = x + ((size_t)(b * Nn + n0)) * Dd;
    for (int i = tid * 4; i < Tt * Dd; i += 128 * 4) {
        float4 v = __ldcs((const float4*)(xb + i));
        int t = i / Dd, d = i - t * Dd;
        float* xp = &Xs[t * 193 + d];
        xp[0] = v.x; xp[1] = v.y; xp[2] = v.z; xp[3] = v.w;
    }
    __syncthreads();

    // phase B: dots + softmax per token (one token per thread)
    int n = n0 + tid;
    float mu = g_mu[b * Nn + n], rs = g_rstd[b * Nn + n];
    float w2s[Kk], ccv[Kk];
#pragma unroll
    for (int k = 0; k < Kk; k++) {
        w2s[k] = __ldg(&g_w2sum[b * Kk + k]);
        ccv[k] = __ldg(&g_cc[b * Kk + k]);
    }
    float acc[Kk];
#pragma unroll
    for (int k = 0; k < Kk; k++) acc[k] = 0.f;
    const float* wt = &g_w2t[b * Dd * KP];
    const float* xrow = &Xs[tid * 193];
#pragma unroll 4
    for (int d = 0; d < Dd; d++) {
        float xv = xrow[d];
        float4 w0 = __ldg((const float4*)(wt + d * KP));
        float4 w1 = __ldg((const float4*)(wt + d * KP + 4));
        float4 w2 = __ldg((const float4*)(wt + d * KP + 8));
        acc[0] = fmaf(xv, w0.x, acc[0]); acc[1] = fmaf(xv, w0.y, acc[1]);
        acc[2] = fmaf(xv, w0.z, acc[2]); acc[3] = fmaf(xv, w0.w, acc[3]);
        acc[4] = fmaf(xv, w1.x, acc[4]); acc[5] = fmaf(xv, w1.y, acc[5]);
        acc[6] = fmaf(xv, w1.z, acc[6]); acc[7] = fmaf(xv, w1.w, acc[7]);
        acc[8] = fmaf(xv, w2.x, acc[8]); acc[9] = fmaf(xv, w2.y, acc[9]);
        acc[10] = fmaf(xv, w2.z, acc[10]);
    }
    float rm = rs * mu;
    float dk[Kk];
#pragma unroll
    for (int k = 0; k < Kk; k++) dk[k] = rs * acc[k] - rm * w2s[k] + ccv[k];
    float mx = dk[0];
#pragma unroll
    for (int k = 1; k < Kk; k++) mx = fmaxf(mx, dk[k]);
    float sum = 0.f;
#pragma unroll
    for (int k = 0; k < Kk; k++) { dk[k] = __expf(dk[k] - mx); sum += dk[k]; }
    float inv = __fdividef(1.0f, sum);
#pragma unroll
    for (int k = 0; k < Kk; k++) dk[k] = fmaf(dk[k], inv, EPSF);
    if (wr) {
#pragma unroll
        for (int k = 0; k < Kk; k++)
            attn_out[((size_t)(b * Kk + k)) * Nn + n] = dk[k];
    }
#pragma unroll
    for (int k = 0; k < Kk; k++) A1[tid * KP + k] = dk[k] * rs;
    // s1/s2 reductions (once per tile)
#pragma unroll
    for (int k = 0; k < Kk; k++) {
        float s1v = dk[k], s2v = dk[k] * rm;
#pragma unroll
        for (int o = 16; o; o >>= 1) {
            s1v += __shfl_xor_sync(~0u, s1v, o);
            s2v += __shfl_xor_sync(~0u, s2v, o);
        }
        if (lane == 0) {
            atomicAdd(&g_s1[b * Kk + k], s1v);
            atomicAdd(&g_s2[b * Kk + k], s2v);
        }
    }
    __syncthreads();

    // phase C: R[k][d] += sum_t A1[t][k] * X[t][d]
    for (int d = tid; d < Dd; d += 128) {
        float acc2[Kk];
#pragma unroll
        for (int k = 0; k < Kk; k++) acc2[k] = 0.f;
#pragma unroll 4
        for (int t = 0; t < Tt; t++) {
            float xv = Xs[t * 193 + d];
            float4 a0 = *(const float4*)&A1[t * KP];
            float4 a1 = *(const float4*)&A1[t * KP + 4];
            float4 a2 = *(const float4*)&A1[t * KP + 8];
            acc2[0] = fmaf(xv, a0.x, acc2[0]); acc2[1] = fmaf(xv, a0.y, acc2[1]);
            acc2[2] = fmaf(xv, a0.z, acc2[2]); acc2[3] = fmaf(xv, a0.w, acc2[3]);
            acc2[4] = fmaf(xv, a1.x, acc2[4]); acc2[5] = fmaf(xv, a1.y, acc2[5]);
            acc2[6] = fmaf(xv, a1.z, acc2[6]); acc2[7] = fmaf(xv, a1.w, acc2[7]);
            acc2[8] = fmaf(xv, a2.x, acc2[8]); acc2[9] = fmaf(xv, a2.y, acc2[9]);
            acc2[10] = fmaf(xv, a2.z, acc2[10]);
        }
#pragma unroll
        for (int k = 0; k < Kk; k++) atomicAdd(&g_R[(b * Kk + k) * Dd + d], acc2[k]);
    }
}

// ---------------- GRU: grid (2 column-halves, 64 batches) ----------------
__global__ __launch_bounds__(288) void k_gru(const float* __restrict__ Wv,
                                             const float* __restrict__ bv,
                                             const float* __restrict__ bih,
                                             const float* __restrict__ bhh,
                                             const float* __restrict__ lnw_in,
                                             const float* __restrict__ lnb_in) {
    __shared__ float uT[Dd * KP], spT[Dd * KP], vT[Dd * KP];
    __shared__ float P0[96 * KP], P1[96 * KP], PXn[96 * KP], PHn[96 * KP];
    __shared__ float sinv[Kk], s2s[Kk];
    int hh = blockIdx.x, b = blockIdx.y, tid = threadIdx.x;
    if (tid < Kk) {
        sinv[tid] = __fdividef(1.0f, g_s1[b * Kk + tid]);
        s2s[tid] = g_s2[b * Kk + tid];
    }
    __syncthreads();
    for (int i = tid; i < Kk * Dd; i += 288) {
        int r = i / Dd, d = i - r * Dd;
        float R = g_R[b * Kk * Dd + i];
        uT[d * KP + r] = lnw_in[d] * (R - s2s[r]) * sinv[r] + lnb_in[d];
        spT[d * KP + r] = g_slots[b * Kk * Dd + i];
    }
    __syncthreads();
    // v = u @ Wv + bv (transposed in smem)
    if (tid < Dd) {
        float acc[Kk];
#pragma unroll
        for (int r = 0; r < Kk; r++) acc[r] = 0.f;
        for (int e = 0; e < Dd; e++) {
            float4 u0 = *(const float4*)&uT[e * KP];
            float4 u1 = *(const float4*)&uT[e * KP + 4];
            float4 u2 = *(const float4*)&uT[e * KP + 8];
            float w = Wv[e * Dd + tid];
            acc[0] = fmaf(u0.x, w, acc[0]); acc[1] = fmaf(u0.y, w, acc[1]);
            acc[2] = fmaf(u0.z, w, acc[2]); acc[3] = fmaf(u0.w, w, acc[3]);
            acc[4] = fmaf(u1.x, w, acc[4]); acc[5] = fmaf(u1.y, w, acc[5]);
            acc[6] = fmaf(u1.z, w, acc[6]); acc[7] = fmaf(u1.w, w, acc[7]);
            acc[8] = fmaf(u2.x, w, acc[8]); acc[9] = fmaf(u2.y, w, acc[9]);
            acc[10] = fmaf(u2.z, w, acc[10]);
        }
        float bvv = bv[tid];
#pragma unroll
        for (int r = 0; r < Kk; r++) vT[tid * KP + r] = acc[r] + bvv;
    }
    __syncthreads();
    // gates for this column-half
    int g = tid / 96, tl = tid - g * 96, t = hh * 96 + tl;
    int j = g * Dd + t;
    float ax[Kk], ah[Kk];
#pragma unroll
    for (int r = 0; r < Kk; r++) { ax[r] = 0.f; ah[r] = 0.f; }
    const float* wi = &g_WihT[j];
    const float* wh = &g_WhhT[j];
    for (int e = 0; e < Dd; e++) {
        float4 v0 = *(const float4*)&vT[e * KP];
        float4 v1 = *(const float4*)&vT[e * KP + 4];
        float4 v2 = *(const float4*)&vT[e * KP + 8];
        float4 s0 = *(const float4*)&spT[e * KP];
        float4 s1 = *(const float4*)&spT[e * KP + 4];
        float4 s2 = *(const float4*)&spT[e * KP + 8];
        float wiv = wi[e * 3 * Dd];
        float whv = wh[e * 3 * Dd];
        ax[0] = fmaf(v0.x, wiv, ax[0]); ah[0] = fmaf(s0.x, whv, ah[0]);
        ax[1] = fmaf(v0.y, wiv, ax[1]); ah[1] = fmaf(s0.y, whv, ah[1]);
        ax[2] = fmaf(v0.z, wiv, ax[2]); ah[2] = fmaf(s0.z, whv, ah[2]);
        ax[3] = fmaf(v0.w, wiv, ax[3]); ah[3] = fmaf(s0.w, whv, ah[3]);
        ax[4] = fmaf(v1.x, wiv, ax[4]); ah[4] = fmaf(s1.x, whv, ah[4]);
        ax[5] = fmaf(v1.y, wiv, ax[5]); ah[5] = fmaf(s1.y, whv, ah[5]);
        ax[6] = fmaf(v1.z, wiv, ax[6]); ah[6] = fmaf(s1.z, whv, ah[6]);
        ax[7] = fmaf(v1.w, wiv, ax[7]); ah[7] = fmaf(s1.w, whv, ah[7]);
        ax[8] = fmaf(v2.x, wiv, ax[8]); ah[8] = fmaf(s2.x, whv, ah[8]);
        ax[9] = fmaf(v2.y, wiv, ax[9]); ah[9] = fmaf(s2.y, whv, ah[9]);
        ax[10] = fmaf(v2.z, wiv, ax[10]); ah[10] = fmaf(s2.z, whv, ah[10]);
    }
    float bi = bih[j], bh = bhh[j];
    if (g == 0) {
#pragma unroll
        for (int r = 0; r < Kk; r++) P0[tl * KP + r] = ax[r] + ah[r] + bi + bh;
    } else if (g == 1) {
#pragma unroll
        for (int r = 0; r < Kk; r++) P1[tl * KP + r] = ax[r] + ah[r] + bi + bh;
    } else {
#pragma unroll
        for (int r = 0; r < Kk; r++) { PXn[tl * KP + r] = ax[r] + bi; PHn[tl * KP + r] = ah[r] + bh; }
    }
    __syncthreads();
    for (int i = tid; i < Kk * 96; i += 288) {
        int r = i / 96, tl2 = i - r * 96, tg = hh * 96 + tl2;
        float rg = 1.0f / (1.0f + __expf(-P0[tl2 * KP + r]));
        float zg = 1.0f / (1.0f + __expf(-P1[tl2 * KP + r]));
        float ng = tanhf(fmaf(rg, PHn[tl2 * KP + r], PXn[tl2 * KP + r]));
        float hp = spT[tg * KP + r];
        g_h[(b * Kk + r) * Dd + tg] = (1.0f - zg) * ng + zg * hp;
    }
}

// ---------------- LN + MLP + residual ----------------
__global__ __launch_bounds__(192) void k_mlp(const float* __restrict__ lnw,
                                             const float* __restrict__ lnb,
                                             const float* __restrict__ W1,
                                             const float* __restrict__ b1,
                                             const float* __restrict__ W2,
                                             const float* __restrict__ b2,
                                             float* __restrict__ slots_out, int last) {
    __shared__ float hT[Dd * KP];
    __shared__ float m1T[HIDn * KP];
    int b = blockIdx.x, t = threadIdx.x, wid = t >> 5, lane = t & 31;
    for (int r = wid; r < Kk; r += 6) {
        float v[6], s = 0.f;
#pragma unroll
        for (int i = 0; i < 6; i++) { v[i] = g_h[(b * Kk + r) * Dd + lane + 32 * i]; s += v[i]; }
#pragma unroll
        for (int o = 16; o; o >>= 1) s += __shfl_xor_sync(~0u, s, o);
        float mu = s * (1.0f / Dd), q = 0.f;
#pragma unroll
        for (int i = 0; i < 6; i++) { float d = v[i] - mu; q += d * d; }
#pragma unroll
        for (int o = 16; o; o >>= 1) q += __shfl_xor_sync(~0u, q, o);
        float rstd = rsqrtf(q * (1.0f / Dd) + LN_EPSF);
#pragma unroll
        for (int i = 0; i < 6; i++) {
            int d = lane + 32 * i;
            hT[d * KP + r] = (v[i] - mu) * rstd * lnw[d] + lnb[d];
        }
    }
    __syncthreads();
    if (t < HIDn) {
        float acc[Kk];
#pragma unroll
        for (int r = 0; r < Kk; r++) acc[r] = 0.f;
        for (int e = 0; e < Dd; e++) {
            float4 h0 = *(const float4*)&hT[e * KP];
            float4 h1 = *(const float4*)&hT[e * KP + 4];
            float4 h2 = *(const float4*)&hT[e * KP + 8];
            float w = W1[e * HIDn + t];
            acc[0] = fmaf(h0.x, w, acc[0]); acc[1] = fmaf(h0.y, w, acc[1]);
            acc[2] = fmaf(h0.z, w, acc[2]); acc[3] = fmaf(h0.w, w, acc[3]);
            acc[4] = fmaf(h1.x, w, acc[4]); acc[5] = fmaf(h1.y, w, acc[5]);
            acc[6] = fmaf(h1.z, w, acc[6]); acc[7] = fmaf(h1.w, w, acc[7]);
            acc[8] = fmaf(h2.x, w, acc[8]); acc[9] = fmaf(h2.y, w, acc[9]);
            acc[10] = fmaf(h2.z, w, acc[10]);
        }
        float b1v = b1[t];
#pragma unroll
        for (int r = 0; r < Kk; r++) m1T[t * KP + r] = fmaxf(acc[r] + b1v, 0.0f);
    }
    __syncthreads();
    float acc[Kk];
#pragma unroll
    for (int r = 0; r < Kk; r++) acc[r] = 0.f;
    for (int h = 0; h < HIDn; h++) {
        float4 m0 = *(const float4*)&m1T[h * KP];
        float4 m1 = *(const float4*)&m1T[h * KP + 4];
        float4 m2 = *(const float4*)&m1T[h * KP + 8];
        float w = W2[h * Dd + t];
        acc[0] = fmaf(m0.x, w, acc[0]); acc[1] = fmaf(m0.y, w, acc[1]);
        acc[2] = fmaf(m0.z, w, acc[2]); acc[3] = fmaf(m0.w, w, acc[3]);
        acc[4] = fmaf(m1.x, w, acc[4]); acc[5] = fmaf(m1.y, w, acc[5]);
        acc[6] = fmaf(m1.z, w, acc[6]); acc[7] = fmaf(m1.w, w, acc[7]);
        acc[8] = fmaf(m2.x, w, acc[8]); acc[9] = fmaf(m2.y, w, acc[9]);
        acc[10] = fmaf(m2.z, w, acc[10]);
    }
    float b2v = b2[t];
#pragma unroll
    for (int r = 0; r < Kk; r++) {
        float o = g_h[(b * Kk + r) * Dd + t] + acc[r] + b2v;
        g_slots[(b * Kk + r) * Dd + t] = o;
        if (last) slots_out[(b * Kk + r) * Dd + t] = o;
    }
}

extern "C" void kernel_launch(void* const* d_in, const int* in_sizes, int n_in,
                              void* d_out, int out_size) {
    const float* inputs = (const float*)d_in[0];
    const float* noise = (const float*)d_in[1];
    const float* smu = (const float*)d_in[2];
    const float* ssig = (const float*)d_in[3];
    const float* ln_in_w = (const float*)d_in[4];
    const float* ln_in_b = (const float*)d_in[5];
    const float* ln_sl_w = (const float*)d_in[6];
    const float* ln_sl_b = (const float*)d_in[7];
    const float* ln_ml_w = (const float*)d_in[8];
    const float* ln_ml_b = (const float*)d_in[9];
    const float* Wq = (const float*)d_in[10];
    const float* bq = (const float*)d_in[11];
    const float* Wk = (const float*)d_in[12];
    const float* bk = (const float*)d_in[13];
    const float* Wv = (const float*)d_in[14];
    const float* bv = (const float*)d_in[15];
    const float* Wih = (const float*)d_in[16];
    const float* Whh = (const float*)d_in[17];
    const float* bih = (const float*)d_in[18];
    const float* bhh = (const float*)d_in[19];
    const float* W1 = (const float*)d_in[20];
    const float* b1 = (const float*)d_in[21];
    const float* W2 = (const float*)d_in[22];
    const float* b2 = (const float*)d_in[23];

    float* out = (float*)d_out;
    float* slots_out = out;
    float* attn_out = out + Bn * Kk * Dd;

    const int ATTN_SMEM = (Tt * 193 + Tt * KP) * 4;  // 104960 bytes
    static bool attr_set = false;
    if (!attr_set) {
        cudaFuncSetAttribute(k_attn, cudaFuncAttributeMaxDynamicSharedMemorySize, ATTN_SMEM);
        attr_set = true;
    }

    k_init<<<384, 256>>>(noise, smu, ssig, Wih, Whh, Wk);
    k_stats<<<(Bn * Nn) / 8, 256>>>(inputs);
    for (int it = 0; it < 3; it++) {
        int last = (it == 2) ? 1 : 0;
        k_pre<<<Bn, 192>>>(ln_sl_w, ln_sl_b, Wq, bq, bk, ln_in_w, ln_in_b);
        k_attn<<<dim3(Nn / Tt, Bn), 128, ATTN_SMEM>>>(inputs, attn_out, last);
        k_gru<<<dim3(2, Bn), 288>>>(Wv, bv, bih, bhh, ln_in_w, ln_in_b);
        k_mlp<<<Bn, 192>>>(ln_ml_w, ln_ml_b, W1, b1, W2, b2, slots_out, last);
    }
}

// round 5
// speedup vs baseline: 1.8404x; 1.7962x over previous
#include <cuda_runtime.h>

#define Bn 64
#define Nn 4096
#define Kk 11
#define KP 12
#define Dd 192
#define HIDn 128
#define Tt 128
#define XST 196
#define EPSF 1e-8f
#define LN_EPSF 1e-5f
#define SCALEF 0.07216878364870323f

typedef unsigned long long ull;

__device__ __forceinline__ ull pk2(float x) {
    ull r; asm("mov.b64 %0, {%1, %1};" : "=l"(r) : "f"(x)); return r;
}
__device__ __forceinline__ ull f2fma(ull a, ull b, ull c) {
    ull d; asm("fma.rn.f32x2 %0, %1, %2, %3;" : "=l"(d) : "l"(a), "l"(b), "l"(c)); return d;
}
__device__ __forceinline__ ull f2add(ull a, ull b) {
    ull d; asm("add.rn.f32x2 %0, %1, %2;" : "=l"(d) : "l"(a), "l"(b)); return d;
}
__device__ __forceinline__ float2 up2(ull v) {
    float lo, hi; asm("mov.b64 {%0, %1}, %2;" : "=f"(lo), "=f"(hi) : "l"(v));
    return make_float2(lo, hi);
}
// acc[j] accumulates k-pair (2j, 2j+1): acc += p[0..11] * broadcast(xx)
__device__ __forceinline__ void fma12(ull acc[6], const float* p, ull xx) {
    ulonglong2 q0 = *(const ulonglong2*)p;
    ulonglong2 q1 = *(const ulonglong2*)(p + 4);
    ulonglong2 q2 = *(const ulonglong2*)(p + 8);
    acc[0] = f2fma(q0.x, xx, acc[0]); acc[1] = f2fma(q0.y, xx, acc[1]);
    acc[2] = f2fma(q1.x, xx, acc[2]); acc[3] = f2fma(q1.y, xx, acc[3]);
    acc[4] = f2fma(q2.x, xx, acc[4]); acc[5] = f2fma(q2.y, xx, acc[5]);
}

__device__ float g_slots[Bn * Kk * Dd];
__device__ float g_h[Bn * Kk * Dd];
__device__ float g_w2k[Bn * Kk * Dd];   // k-major: [b][k][d]
__device__ float g_w2sum[Bn * Kk];
__device__ float g_cc[Bn * Kk];
__device__ float g_R[Bn * Kk * Dd];
__device__ float g_s1[Bn * Kk];
__device__ float g_s2[Bn * Kk];
__device__ float g_WihT[Dd * 3 * Dd];
__device__ float g_WhhT[Dd * 3 * Dd];
__device__ float g_WkT[Dd * Dd];

// ---------------- init ----------------
__global__ void k_init(const float* __restrict__ noise, const float* __restrict__ smu,
                       const float* __restrict__ ssig, const float* __restrict__ Wih,
                       const float* __restrict__ Whh, const float* __restrict__ Wk) {
    const int T0 = Bn * Kk * Dd;
    const int T1 = T0 + 3 * Dd * Dd;
    const int T2 = T1 + 3 * Dd * Dd;
    const int T3 = T2 + Dd * Dd;
    for (int i = blockIdx.x * blockDim.x + threadIdx.x; i < T3; i += gridDim.x * blockDim.x) {
        if (i < T0) { int d = i % Dd; g_slots[i] = smu[d] + ssig[d] * noise[i]; }
        else if (i < T1) { int i2 = i - T0; g_WihT[(i2 % Dd) * (3 * Dd) + i2 / Dd] = Wih[i2]; }
        else if (i < T2) { int i2 = i - T1; g_WhhT[(i2 % Dd) * (3 * Dd) + i2 / Dd] = Whh[i2]; }
        else { int i2 = i - T2; g_WkT[(i2 % Dd) * Dd + i2 / Dd] = Wk[i2]; }
    }
}

// ---------------- per-iter slot preprocessing ----------------
__global__ __launch_bounds__(192) void k_pre(const float* __restrict__ lnw_s,
                                             const float* __restrict__ lnb_s,
                                             const float* __restrict__ Wq,
                                             const float* __restrict__ bq,
                                             const float* __restrict__ bk,
                                             const float* __restrict__ lnw_in,
                                             const float* __restrict__ lnb_in) {
    __shared__ float snt[Dd * KP];
    __shared__ float qT[Dd * KP];
    __shared__ float red[24];
    int b = blockIdx.x, t = threadIdx.x, wid = t >> 5, lane = t & 31;
    if (t < 24) red[t] = 0.f;
    snt[t * KP + 11] = 0.f;

    // LN of slots: warp-per-slot
    for (int r = wid; r < Kk; r += 6) {
        float v[6], s = 0.f;
#pragma unroll
        for (int i = 0; i < 6; i++) { v[i] = g_slots[(b * Kk + r) * Dd + lane + 32 * i]; s += v[i]; }
#pragma unroll
        for (int o = 16; o; o >>= 1) s += __shfl_xor_sync(~0u, s, o);
        float mu = s * (1.0f / Dd), q = 0.f;
#pragma unroll
        for (int i = 0; i < 6; i++) { float d = v[i] - mu; q += d * d; }
#pragma unroll
        for (int o = 16; o; o >>= 1) q += __shfl_xor_sync(~0u, q, o);
        float rstd = rsqrtf(q * (1.0f / Dd) + LN_EPSF);
#pragma unroll
        for (int i = 0; i < 6; i++) {
            int d = lane + 32 * i;
            snt[d * KP + r] = (v[i] - mu) * rstd * lnw_s[d] + lnb_s[d];
        }
    }
    __syncthreads();

    // q[r][t] = sn[r] . Wq[:,t] + bq[t]
    ull a6[6];
#pragma unroll
    for (int j = 0; j < 6; j++) a6[j] = 0ull;
    for (int e = 0; e < Dd; e++) fma12(a6, &snt[e * KP], pk2(Wq[e * Dd + t]));
    float qa[Kk];
    float bqv = bq[t];
#pragma unroll
    for (int j = 0; j < 6; j++) {
        float2 f = up2(a6[j]);
        if (2 * j < Kk) qa[2 * j] = f.x + bqv;
        if (2 * j + 1 < Kk) qa[2 * j + 1] = f.y + bqv;
    }
#pragma unroll
    for (int r = 0; r < Kk; r++) qT[t * KP + r] = qa[r];
    qT[t * KP + 11] = 0.f;
    __syncthreads();

    // qt[r][t] = sum_d WkT[d][t] * q[r][d]
#pragma unroll
    for (int j = 0; j < 6; j++) a6[j] = 0ull;
    for (int d = 0; d < Dd; d++) fma12(a6, &qT[d * KP], pk2(g_WkT[d * Dd + t]));
    float qt[Kk];
#pragma unroll
    for (int j = 0; j < 6; j++) {
        float2 f = up2(a6[j]);
        if (2 * j < Kk) qt[2 * j] = f.x;
        if (2 * j + 1 < Kk) qt[2 * j + 1] = f.y;
    }
    float lwv = lnw_in[t], lbv = lnb_in[t], bkv = bk[t];
    float ws[Kk], cp[Kk];
#pragma unroll
    for (int r = 0; r < Kk; r++) {
        float w2 = qt[r] * SCALEF * lwv;
        g_w2k[(b * Kk + r) * Dd + t] = w2;
        ws[r] = w2;
        cp[r] = (lbv * qt[r] + qa[r] * bkv) * SCALEF;
    }
#pragma unroll
    for (int r = 0; r < Kk; r++) {
        float a = ws[r], c = cp[r];
#pragma unroll
        for (int o = 16; o; o >>= 1) {
            a += __shfl_xor_sync(~0u, a, o);
            c += __shfl_xor_sync(~0u, c, o);
        }
        if (lane == 0) { atomicAdd(&red[r], a); atomicAdd(&red[12 + r], c); }
    }
    __syncthreads();
    if (t < Kk) {
        g_w2sum[b * Kk + t] = red[t];
        g_cc[b * Kk + t] = red[12 + t];
        g_s1[b * Kk + t] = 0.f;
        g_s2[b * Kk + t] = 0.f;
    }
    for (int i = t; i < Kk * Dd; i += 192) g_R[b * Kk * Dd + i] = 0.f;
}

// ---------------- attention pass ----------------
__global__ __launch_bounds__(128) void k_attn(const float* __restrict__ x,
                                              float* __restrict__ attn_out, int wr) {
    extern __shared__ float sm[];
    float* Xs = sm;                 // Tt rows, stride XST
    float* Ws = sm + Tt * XST;      // [k][192] (phase B), aliased by A1 (phase C)
    float* A1 = Ws;                 // Tt x KP
    int b = blockIdx.y, tid = threadIdx.x, lane = tid & 31;
    int n0 = blockIdx.x * Tt;

    // load raw x tile + w2 rows
    const float* xb = x + ((size_t)(b * Nn + n0)) * Dd;
    for (int i = tid * 4; i < Tt * Dd; i += 128 * 4) {
        float4 v = __ldcs((const float4*)(xb + i));
        int t = i / Dd, d = i - t * Dd;
        *(float4*)&Xs[t * XST + d] = v;
    }
    const float* wsrc = g_w2k + b * Kk * Dd;
    for (int i = tid; i < Kk * Dd; i += 128) Ws[i] = wsrc[i];
    __syncthreads();

    // phase B: stats + dots (token per thread), pairs along d
    ull aA[Kk], aB[Kk];
#pragma unroll
    for (int k = 0; k < Kk; k++) { aA[k] = 0ull; aB[k] = 0ull; }
    ull sSa = 0ull, sSb = 0ull, sQa = 0ull, sQb = 0ull;
    const ulonglong2* xr2 = (const ulonglong2*)(Xs + tid * XST);
#pragma unroll 4
    for (int c = 0; c < 48; c++) {
        ulonglong2 xv = xr2[c];
        sSa = f2add(sSa, xv.x); sSb = f2add(sSb, xv.y);
        sQa = f2fma(xv.x, xv.x, sQa); sQb = f2fma(xv.y, xv.y, sQb);
#pragma unroll
        for (int k = 0; k < Kk; k++) {
            ulonglong2 wv = *(const ulonglong2*)&Ws[k * Dd + c * 4];
            aA[k] = f2fma(xv.x, wv.x, aA[k]);
            aB[k] = f2fma(xv.y, wv.y, aB[k]);
        }
    }
    float2 sf = up2(f2add(sSa, sSb));
    float2 qf = up2(f2add(sQa, sQb));
    float mu = (sf.x + sf.y) * (1.0f / Dd);
    float ex2 = (qf.x + qf.y) * (1.0f / Dd);
    float rs = rsqrtf(ex2 - mu * mu + LN_EPSF);
    float rm = rs * mu;
    float dk[Kk];
#pragma unroll
    for (int k = 0; k < Kk; k++) {
        float2 fa = up2(aA[k]), fb = up2(aB[k]);
        float dot = (fa.x + fa.y) + (fb.x + fb.y);
        dk[k] = rs * dot - rm * __ldg(&g_w2sum[b * Kk + k]) + __ldg(&g_cc[b * Kk + k]);
    }
    float mx = dk[0];
#pragma unroll
    for (int k = 1; k < Kk; k++) mx = fmaxf(mx, dk[k]);
    float sum = 0.f;
#pragma unroll
    for (int k = 0; k < Kk; k++) { dk[k] = __expf(dk[k] - mx); sum += dk[k]; }
    float inv = __fdividef(1.0f, sum);
#pragma unroll
    for (int k = 0; k < Kk; k++) dk[k] = fmaf(dk[k], inv, EPSF);
    int n = n0 + tid;
    if (wr) {
#pragma unroll
        for (int k = 0; k < Kk; k++)
            attn_out[((size_t)(b * Kk + k)) * Nn + n] = dk[k];
    }
    // s1/s2 reductions
#pragma unroll
    for (int k = 0; k < Kk; k++) {
        float s1v = dk[k], s2v = dk[k] * rm;
#pragma unroll
        for (int o = 16; o; o >>= 1) {
            s1v += __shfl_xor_sync(~0u, s1v, o);
            s2v += __shfl_xor_sync(~0u, s2v, o);
        }
        if (lane == 0) {
            atomicAdd(&g_s1[b * Kk + k], s1v);
            atomicAdd(&g_s2[b * Kk + k], s2v);
        }
    }
    __syncthreads();  // all dot reads of Ws done
#pragma unroll
    for (int k = 0; k < Kk; k++) A1[tid * KP + k] = dk[k] * rs;
    A1[tid * KP + 11] = 0.f;
    __syncthreads();

    // phase C: R[k][d] += sum_t A1[t][k] * X[t][d]
    for (int d = tid; d < Dd; d += 128) {
        ull c6[6];
#pragma unroll
        for (int j = 0; j < 6; j++) c6[j] = 0ull;
#pragma unroll 4
        for (int t = 0; t < Tt; t++) {
            fma12(c6, &A1[t * KP], pk2(Xs[t * XST + d]));
        }
#pragma unroll
        for (int j = 0; j < 6; j++) {
            float2 f = up2(c6[j]);
            atomicAdd(&g_R[(b * Kk + 2 * j) * Dd + d], f.x);
            if (2 * j + 1 < Kk) atomicAdd(&g_R[(b * Kk + 2 * j + 1) * Dd + d], f.y);
        }
    }
}

// ---------------- GRU ----------------
__global__ __launch_bounds__(288) void k_gru(const float* __restrict__ Wv,
                                             const float* __restrict__ bv,
                                             const float* __restrict__ bih,
                                             const float* __restrict__ bhh,
                                             const float* __restrict__ lnw_in,
                                             const float* __restrict__ lnb_in) {
    __shared__ float uT[Dd * KP], spT[Dd * KP], vT[Dd * KP];
    __shared__ float P0[96 * KP], P1[96 * KP], PXn[96 * KP], PHn[96 * KP];
    __shared__ float sinv[Kk], s2s[Kk];
    int hh = blockIdx.x, b = blockIdx.y, tid = threadIdx.x;
    if (tid < Kk) {
        sinv[tid] = __fdividef(1.0f, g_s1[b * Kk + tid]);
        s2s[tid] = g_s2[b * Kk + tid];
    }
    __syncthreads();
    for (int i = tid; i < Dd; i += 288) { uT[i * KP + 11] = 0.f; spT[i * KP + 11] = 0.f; }
    for (int i = tid; i < Kk * Dd; i += 288) {
        int r = i / Dd, d = i - r * Dd;
        float R = g_R[b * Kk * Dd + i];
        uT[d * KP + r] = lnw_in[d] * (R - s2s[r]) * sinv[r] + lnb_in[d];
        spT[d * KP + r] = g_slots[b * Kk * Dd + i];
    }
    __syncthreads();
    // v = u @ Wv + bv
    if (tid < Dd) {
        ull a6[6];
#pragma unroll
        for (int j = 0; j < 6; j++) a6[j] = 0ull;
        for (int e = 0; e < Dd; e++) fma12(a6, &uT[e * KP], pk2(Wv[e * Dd + tid]));
        float bvv = bv[tid];
#pragma unroll
        for (int j = 0; j < 6; j++) {
            float2 f = up2(a6[j]);
            if (2 * j < Kk) vT[tid * KP + 2 * j] = f.x + bvv;
            if (2 * j + 1 < Kk) vT[tid * KP + 2 * j + 1] = f.y + bvv;
        }
        vT[tid * KP + 11] = 0.f;
    }
    __syncthreads();
    // gates for this column-half
    int g = tid / 96, tl = tid - g * 96, t = hh * 96 + tl;
    int j = g * Dd + t;
    ull ax6[6], ah6[6];
#pragma unroll
    for (int jj = 0; jj < 6; jj++) { ax6[jj] = 0ull; ah6[jj] = 0ull; }
    const float* wi = &g_WihT[j];
    const float* wh = &g_WhhT[j];
    for (int e = 0; e < Dd; e++) {
        fma12(ax6, &vT[e * KP], pk2(wi[e * 3 * Dd]));
        fma12(ah6, &spT[e * KP], pk2(wh[e * 3 * Dd]));
    }
    float axf[KP], ahf[KP];
#pragma unroll
    for (int jj = 0; jj < 6; jj++) {
        float2 fx = up2(ax6[jj]), fh = up2(ah6[jj]);
        axf[2 * jj] = fx.x; axf[2 * jj + 1] = fx.y;
        ahf[2 * jj] = fh.x; ahf[2 * jj + 1] = fh.y;
    }
    float bi = bih[j], bh = bhh[j];
    if (g == 0) {
#pragma unroll
        for (int r = 0; r < Kk; r++) P0[tl * KP + r] = axf[r] + ahf[r] + bi + bh;
    } else if (g == 1) {
#pragma unroll
        for (int r = 0; r < Kk; r++) P1[tl * KP + r] = axf[r] + ahf[r] + bi + bh;
    } else {
#pragma unroll
        for (int r = 0; r < Kk; r++) { PXn[tl * KP + r] = axf[r] + bi; PHn[tl * KP + r] = ahf[r] + bh; }
    }
    __syncthreads();
    for (int i = tid; i < Kk * 96; i += 288) {
        int r = i / 96, tl2 = i - r * 96, tg = hh * 96 + tl2;
        float rg = 1.0f / (1.0f + __expf(-P0[tl2 * KP + r]));
        float zg = 1.0f / (1.0f + __expf(-P1[tl2 * KP + r]));
        float ng = tanhf(fmaf(rg, PHn[tl2 * KP + r], PXn[tl2 * KP + r]));
        float hp = spT[tg * KP + r];
        g_h[(b * Kk + r) * Dd + tg] = (1.0f - zg) * ng + zg * hp;
    }
}

// ---------------- LN + MLP + residual ----------------
__global__ __launch_bounds__(192) void k_mlp(const float* __restrict__ lnw,
                                             const float* __restrict__ lnb,
                                             const float* __restrict__ W1,
                                             const float* __restrict__ b1,
                                             const float* __restrict__ W2,
                                             const float* __restrict__ b2,
                                             float* __restrict__ slots_out, int last) {
    __shared__ float hT[Dd * KP];
    __shared__ float m1T[HIDn * KP];
    int b = blockIdx.x, t = threadIdx.x, wid = t >> 5, lane = t & 31;
    hT[t * KP + 11] = 0.f;
    if (t < HIDn) m1T[t * KP + 11] = 0.f;
    for (int r = wid; r < Kk; r += 6) {
        float v[6], s = 0.f;
#pragma unroll
        for (int i = 0; i < 6; i++) { v[i] = g_h[(b * Kk + r) * Dd + lane + 32 * i]; s += v[i]; }
#pragma unroll
        for (int o = 16; o; o >>= 1) s += __shfl_xor_sync(~0u, s, o);
        float mu = s * (1.0f / Dd), q = 0.f;
#pragma unroll
        for (int i = 0; i < 6; i++) { float d = v[i] - mu; q += d * d; }
#pragma unroll
        for (int o = 16; o; o >>= 1) q += __shfl_xor_sync(~0u, q, o);
        float rstd = rsqrtf(q * (1.0f / Dd) + LN_EPSF);
#pragma unroll
        for (int i = 0; i < 6; i++) {
            int d = lane + 32 * i;
            hT[d * KP + r] = (v[i] - mu) * rstd * lnw[d] + lnb[d];
        }
    }
    __syncthreads();
    if (t < HIDn) {
        ull a6[6];
#pragma unroll
        for (int j = 0; j < 6; j++) a6[j] = 0ull;
        for (int e = 0; e < Dd; e++) fma12(a6, &hT[e * KP], pk2(W1[e * HIDn + t]));
        float b1v = b1[t];
#pragma unroll
        for (int j = 0; j < 6; j++) {
            float2 f = up2(a6[j]);
            if (2 * j < Kk) m1T[t * KP + 2 * j] = fmaxf(f.x + b1v, 0.0f);
            if (2 * j + 1 < Kk) m1T[t * KP + 2 * j + 1] = fmaxf(f.y + b1v, 0.0f);
        }
    }
    __syncthreads();
    ull a6[6];
#pragma unroll
    for (int j = 0; j < 6; j++) a6[j] = 0ull;
    for (int h = 0; h < HIDn; h++) fma12(a6, &m1T[h * KP], pk2(W2[h * Dd + t]));
    float acc[Kk];
#pragma unroll
    for (int j = 0; j < 6; j++) {
        float2 f = up2(a6[j]);
        if (2 * j < Kk) acc[2 * j] = f.x;
        if (2 * j + 1 < Kk) acc[2 * j + 1] = f.y;
    }
    float b2v = b2[t];
#pragma unroll
    for (int r = 0; r < Kk; r++) {
        float o = g_h[(b * Kk + r) * Dd + t] + acc[r] + b2v;
        g_slots[(b * Kk + r) * Dd + t] = o;
        if (last) slots_out[(b * Kk + r) * Dd + t] = o;
    }
}

extern "C" void kernel_launch(void* const* d_in, const int* in_sizes, int n_in,
                              void* d_out, int out_size) {
    const float* inputs = (const float*)d_in[0];
    const float* noise = (const float*)d_in[1];
    const float* smu = (const float*)d_in[2];
    const float* ssig = (const float*)d_in[3];
    const float* ln_in_w = (const float*)d_in[4];
    const float* ln_in_b = (const float*)d_in[5];
    const float* ln_sl_w = (const float*)d_in[6];
    const float* ln_sl_b = (const float*)d_in[7];
    const float* ln_ml_w = (const float*)d_in[8];
    const float* ln_ml_b = (const float*)d_in[9];
    const float* Wq = (const float*)d_in[10];
    const float* bq = (const float*)d_in[11];
    const float* Wk = (const float*)d_in[12];
    const float* bk = (const float*)d_in[13];
    const float* Wv = (const float*)d_in[14];
    const float* bv = (const float*)d_in[15];
    const float* Wih = (const float*)d_in[16];
    const float* Whh = (const float*)d_in[17];
    const float* bih = (const float*)d_in[18];
    const float* bhh = (const float*)d_in[19];
    const float* W1 = (const float*)d_in[20];
    const float* b1 = (const float*)d_in[21];
    const float* W2 = (const float*)d_in[22];
    const float* b2 = (const float*)d_in[23];

    float* out = (float*)d_out;
    float* slots_out = out;
    float* attn_out = out + Bn * Kk * Dd;

    const int ATTN_SMEM = (Tt * XST + Kk * Dd) * 4;  // 108,800 bytes
    static bool attr_set = false;
    if (!attr_set) {
        cudaFuncSetAttribute(k_attn, cudaFuncAttributeMaxDynamicSharedMemorySize, ATTN_SMEM);
        attr_set = true;
    }

    k_init<<<384, 256>>>(noise, smu, ssig, Wih, Whh, Wk);
    for (int it = 0; it < 3; it++) {
        int last = (it == 2) ? 1 : 0;
        k_pre<<<Bn, 192>>>(ln_sl_w, ln_sl_b, Wq, bq, bk, ln_in_w, ln_in_b);
        k_attn<<<dim3(Nn / Tt, Bn), 128, ATTN_SMEM>>>(inputs, attn_out, last);
        k_gru<<<dim3(2, Bn), 288>>>(Wv, bv, bih, bhh, ln_in_w, ln_in_b);
        k_mlp<<<Bn, 192>>>(ln_ml_w, ln_ml_b, W1, b1, W2, b2, slots_out, last);
    }
}

// round 6
// speedup vs baseline: 1.8608x; 1.0111x over previous
#include <cuda_runtime.h>

#define Bn 64
#define Nn 4096
#define Kk 11
#define KP 12
#define Dd 192
#define HIDn 128
#define Tt 128
#define XST 196
#define EPSF 1e-8f
#define LN_EPSF 1e-5f
#define SCALEF 0.07216878364870323f

typedef unsigned long long ull;

__device__ __forceinline__ ull pk2(float x) {
    ull r; asm("mov.b64 %0, {%1, %1};" : "=l"(r) : "f"(x)); return r;
}
__device__ __forceinline__ ull f2fma(ull a, ull b, ull c) {
    ull d; asm("fma.rn.f32x2 %0, %1, %2, %3;" : "=l"(d) : "l"(a), "l"(b), "l"(c)); return d;
}
__device__ __forceinline__ ull f2add(ull a, ull b) {
    ull d; asm("add.rn.f32x2 %0, %1, %2;" : "=l"(d) : "l"(a), "l"(b)); return d;
}
__device__ __forceinline__ float2 up2(ull v) {
    float lo, hi; asm("mov.b64 {%0, %1}, %2;" : "=f"(lo), "=f"(hi) : "l"(v));
    return make_float2(lo, hi);
}
__device__ __forceinline__ void fma12(ull acc[6], const float* p, ull xx) {
    ulonglong2 q0 = *(const ulonglong2*)p;
    ulonglong2 q1 = *(const ulonglong2*)(p + 4);
    ulonglong2 q2 = *(const ulonglong2*)(p + 8);
    acc[0] = f2fma(q0.x, xx, acc[0]); acc[1] = f2fma(q0.y, xx, acc[1]);
    acc[2] = f2fma(q1.x, xx, acc[2]); acc[3] = f2fma(q1.y, xx, acc[3]);
    acc[4] = f2fma(q2.x, xx, acc[4]); acc[5] = f2fma(q2.y, xx, acc[5]);
}

__device__ float g_slots[Bn * Kk * Dd];
__device__ float g_h[Bn * Kk * Dd];
__device__ float g_w2k[Bn * Kk * Dd];
__device__ float g_w2sum[Bn * Kk];
__device__ float g_cc[Bn * Kk];
__device__ float g_R[Bn * Kk * Dd];
__device__ float g_s1[Bn * Kk];
__device__ float g_s2[Bn * Kk];
__device__ float g_WqT[Dd * Dd];     // [t][e]
__device__ float g_WvT[Dd * Dd];     // [t][e]
__device__ float g_W1T[HIDn * Dd];   // [t][e]
__device__ float g_W2T[Dd * HIDn];   // [t][h]

// ---------------- init ----------------
__global__ void k_init(const float* __restrict__ noise, const float* __restrict__ smu,
                       const float* __restrict__ ssig, const float* __restrict__ Wq,
                       const float* __restrict__ Wv, const float* __restrict__ W1,
                       const float* __restrict__ W2) {
    const int T0 = Bn * Kk * Dd;
    const int T1 = T0 + Dd * Dd;
    const int T2 = T1 + Dd * Dd;
    const int T3 = T2 + Dd * HIDn;
    const int T4 = T3 + HIDn * Dd;
    for (int i = blockIdx.x * blockDim.x + threadIdx.x; i < T4; i += gridDim.x * blockDim.x) {
        if (i < T0) { int d = i % Dd; g_slots[i] = smu[d] + ssig[d] * noise[i]; }
        else if (i < T1) { int i2 = i - T0; g_WqT[(i2 % Dd) * Dd + i2 / Dd] = Wq[i2]; }
        else if (i < T2) { int i2 = i - T1; g_WvT[(i2 % Dd) * Dd + i2 / Dd] = Wv[i2]; }
        else if (i < T3) { int i2 = i - T2; g_W1T[(i2 % HIDn) * Dd + i2 / HIDn] = W1[i2]; }
        else { int i2 = i - T3; g_W2T[(i2 % Dd) * HIDn + i2 / Dd] = W2[i2]; }
    }
}

// ---------------- per-iter slot preprocessing ----------------
__global__ __launch_bounds__(192) void k_pre(const float* __restrict__ lnw_s,
                                             const float* __restrict__ lnb_s,
                                             const float* __restrict__ bq,
                                             const float* __restrict__ Wk,
                                             const float* __restrict__ bk,
                                             const float* __restrict__ lnw_in,
                                             const float* __restrict__ lnb_in) {
    __shared__ float snt[Dd * KP];
    __shared__ float qT[Dd * KP];
    __shared__ float red[24];
    int b = blockIdx.x, t = threadIdx.x, wid = t >> 5, lane = t & 31;
    if (t < 24) red[t] = 0.f;
    snt[t * KP + 11] = 0.f;

    for (int r = wid; r < Kk; r += 6) {
        float v[6], s = 0.f;
#pragma unroll
        for (int i = 0; i < 6; i++) { v[i] = g_slots[(b * Kk + r) * Dd + lane + 32 * i]; s += v[i]; }
#pragma unroll
        for (int o = 16; o; o >>= 1) s += __shfl_xor_sync(~0u, s, o);
        float mu = s * (1.0f / Dd), q = 0.f;
#pragma unroll
        for (int i = 0; i < 6; i++) { float d = v[i] - mu; q += d * d; }
#pragma unroll
        for (int o = 16; o; o >>= 1) q += __shfl_xor_sync(~0u, q, o);
        float rstd = rsqrtf(q * (1.0f / Dd) + LN_EPSF);
#pragma unroll
        for (int i = 0; i < 6; i++) {
            int d = lane + 32 * i;
            snt[d * KP + r] = (v[i] - mu) * rstd * lnw_s[d] + lnb_s[d];
        }
    }
    __syncthreads();

    // q[r][t] = sn[r] . Wq[:,t] + bq[t]   (WqT row t contiguous)
    ull a6[6];
#pragma unroll
    for (int j = 0; j < 6; j++) a6[j] = 0ull;
    {
        const float4* w4 = (const float4*)(g_WqT + t * Dd);
#pragma unroll 4
        for (int c = 0; c < 48; c++) {
            float4 w = __ldg(&w4[c]);
            fma12(a6, &snt[(4 * c + 0) * KP], pk2(w.x));
            fma12(a6, &snt[(4 * c + 1) * KP], pk2(w.y));
            fma12(a6, &snt[(4 * c + 2) * KP], pk2(w.z));
            fma12(a6, &snt[(4 * c + 3) * KP], pk2(w.w));
        }
    }
    float qa[Kk];
    float bqv = bq[t];
#pragma unroll
    for (int j = 0; j < 6; j++) {
        float2 f = up2(a6[j]);
        if (2 * j < Kk) qa[2 * j] = f.x + bqv;
        if (2 * j + 1 < Kk) qa[2 * j + 1] = f.y + bqv;
    }
#pragma unroll
    for (int r = 0; r < Kk; r++) qT[t * KP + r] = qa[r];
    qT[t * KP + 11] = 0.f;
    __syncthreads();

    // qt[r][t] = Wk[t,:] . q[r,:]   (Wk row t contiguous)
#pragma unroll
    for (int j = 0; j < 6; j++) a6[j] = 0ull;
    {
        const float4* w4 = (const float4*)(Wk + t * Dd);
#pragma unroll 4
        for (int c = 0; c < 48; c++) {
            float4 w = __ldg(&w4[c]);
            fma12(a6, &qT[(4 * c + 0) * KP], pk2(w.x));
            fma12(a6, &qT[(4 * c + 1) * KP], pk2(w.y));
            fma12(a6, &qT[(4 * c + 2) * KP], pk2(w.z));
            fma12(a6, &qT[(4 * c + 3) * KP], pk2(w.w));
        }
    }
    float qt[Kk];
#pragma unroll
    for (int j = 0; j < 6; j++) {
        float2 f = up2(a6[j]);
        if (2 * j < Kk) qt[2 * j] = f.x;
        if (2 * j + 1 < Kk) qt[2 * j + 1] = f.y;
    }
    float lwv = lnw_in[t], lbv = lnb_in[t], bkv = bk[t];
    float ws[Kk], cp[Kk];
#pragma unroll
    for (int r = 0; r < Kk; r++) {
        float w2 = qt[r] * SCALEF * lwv;
        g_w2k[(b * Kk + r) * Dd + t] = w2;
        ws[r] = w2;
        cp[r] = (lbv * qt[r] + qa[r] * bkv) * SCALEF;
    }
#pragma unroll
    for (int r = 0; r < Kk; r++) {
        float a = ws[r], c = cp[r];
#pragma unroll
        for (int o = 16; o; o >>= 1) {
            a += __shfl_xor_sync(~0u, a, o);
            c += __shfl_xor_sync(~0u, c, o);
        }
        if (lane == 0) { atomicAdd(&red[r], a); atomicAdd(&red[12 + r], c); }
    }
    __syncthreads();
    if (t < Kk) {
        g_w2sum[b * Kk + t] = red[t];
        g_cc[b * Kk + t] = red[12 + t];
        g_s1[b * Kk + t] = 0.f;
        g_s2[b * Kk + t] = 0.f;
    }
    for (int i = t; i < Kk * Dd; i += 192) g_R[b * Kk * Dd + i] = 0.f;
}

// ---------------- attention pass ----------------
__global__ __launch_bounds__(128) void k_attn(const float* __restrict__ x,
                                              float* __restrict__ attn_out, int wr) {
    extern __shared__ float sm[];
    float* Xs = sm;
    float* Ws = sm + Tt * XST;
    float* A1 = Ws;
    int b = blockIdx.y, tid = threadIdx.x, lane = tid & 31;
    int n0 = blockIdx.x * Tt;

    const float* xb = x + ((size_t)(b * Nn + n0)) * Dd;
    for (int i = tid * 4; i < Tt * Dd; i += 128 * 4) {
        float4 v = __ldcs((const float4*)(xb + i));
        int t = i / Dd, d = i - t * Dd;
        *(float4*)&Xs[t * XST + d] = v;
    }
    const float* wsrc = g_w2k + b * Kk * Dd;
    for (int i = tid; i < Kk * Dd; i += 128) Ws[i] = wsrc[i];
    __syncthreads();

    ull aA[Kk], aB[Kk];
#pragma unroll
    for (int k = 0; k < Kk; k++) { aA[k] = 0ull; aB[k] = 0ull; }
    ull sSa = 0ull, sSb = 0ull, sQa = 0ull, sQb = 0ull;
    const ulonglong2* xr2 = (const ulonglong2*)(Xs + tid * XST);
#pragma unroll 4
    for (int c = 0; c < 48; c++) {
        ulonglong2 xv = xr2[c];
        sSa = f2add(sSa, xv.x); sSb = f2add(sSb, xv.y);
        sQa = f2fma(xv.x, xv.x, sQa); sQb = f2fma(xv.y, xv.y, sQb);
#pragma unroll
        for (int k = 0; k < Kk; k++) {
            ulonglong2 wv = *(const ulonglong2*)&Ws[k * Dd + c * 4];
            aA[k] = f2fma(xv.x, wv.x, aA[k]);
            aB[k] = f2fma(xv.y, wv.y, aB[k]);
        }
    }
    float2 sf = up2(f2add(sSa, sSb));
    float2 qf = up2(f2add(sQa, sQb));
    float mu = (sf.x + sf.y) * (1.0f / Dd);
    float ex2 = (qf.x + qf.y) * (1.0f / Dd);
    float rs = rsqrtf(ex2 - mu * mu + LN_EPSF);
    float rm = rs * mu;
    float dk[Kk];
#pragma unroll
    for (int k = 0; k < Kk; k++) {
        float2 fa = up2(aA[k]), fb = up2(aB[k]);
        float dot = (fa.x + fa.y) + (fb.x + fb.y);
        dk[k] = rs * dot - rm * __ldg(&g_w2sum[b * Kk + k]) + __ldg(&g_cc[b * Kk + k]);
    }
    float mx = dk[0];
#pragma unroll
    for (int k = 1; k < Kk; k++) mx = fmaxf(mx, dk[k]);
    float sum = 0.f;
#pragma unroll
    for (int k = 0; k < Kk; k++) { dk[k] = __expf(dk[k] - mx); sum += dk[k]; }
    float inv = __fdividef(1.0f, sum);
#pragma unroll
    for (int k = 0; k < Kk; k++) dk[k] = fmaf(dk[k], inv, EPSF);
    int n = n0 + tid;
    if (wr) {
#pragma unroll
        for (int k = 0; k < Kk; k++)
            attn_out[((size_t)(b * Kk + k)) * Nn + n] = dk[k];
    }
#pragma unroll
    for (int k = 0; k < Kk; k++) {
        float s1v = dk[k], s2v = dk[k] * rm;
#pragma unroll
        for (int o = 16; o; o >>= 1) {
            s1v += __shfl_xor_sync(~0u, s1v, o);
            s2v += __shfl_xor_sync(~0u, s2v, o);
        }
        if (lane == 0) {
            atomicAdd(&g_s1[b * Kk + k], s1v);
            atomicAdd(&g_s2[b * Kk + k], s2v);
        }
    }
    __syncthreads();
#pragma unroll
    for (int k = 0; k < Kk; k++) A1[tid * KP + k] = dk[k] * rs;
    A1[tid * KP + 11] = 0.f;
    __syncthreads();

    for (int d = tid; d < Dd; d += 128) {
        ull c6[6];
#pragma unroll
        for (int j = 0; j < 6; j++) c6[j] = 0ull;
#pragma unroll 4
        for (int t = 0; t < Tt; t++) {
            fma12(c6, &A1[t * KP], pk2(Xs[t * XST + d]));
        }
#pragma unroll
        for (int j = 0; j < 6; j++) {
            float2 f = up2(c6[j]);
            atomicAdd(&g_R[(b * Kk + 2 * j) * Dd + d], f.x);
            if (2 * j + 1 < Kk) atomicAdd(&g_R[(b * Kk + 2 * j + 1) * Dd + d], f.y);
        }
    }
}

// ---------------- GRU ----------------
__global__ __launch_bounds__(288) void k_gru(const float* __restrict__ bv,
                                             const float* __restrict__ Wih,
                                             const float* __restrict__ Whh,
                                             const float* __restrict__ bih,
                                             const float* __restrict__ bhh,
                                             const float* __restrict__ lnw_in,
                                             const float* __restrict__ lnb_in) {
    __shared__ float uT[Dd * KP], spT[Dd * KP], vT[Dd * KP];
    __shared__ float P0[96 * KP], P1[96 * KP], PXn[96 * KP], PHn[96 * KP];
    __shared__ float sinv[Kk], s2s[Kk];
    int hh = blockIdx.x, b = blockIdx.y, tid = threadIdx.x;
    if (tid < Kk) {
        sinv[tid] = __fdividef(1.0f, g_s1[b * Kk + tid]);
        s2s[tid] = g_s2[b * Kk + tid];
    }
    __syncthreads();
    for (int i = tid; i < Dd; i += 288) { uT[i * KP + 11] = 0.f; spT[i * KP + 11] = 0.f; }
    for (int i = tid; i < Kk * Dd; i += 288) {
        int r = i / Dd, d = i - r * Dd;
        float R = g_R[b * Kk * Dd + i];
        uT[d * KP + r] = lnw_in[d] * (R - s2s[r]) * sinv[r] + lnb_in[d];
        spT[d * KP + r] = g_slots[b * Kk * Dd + i];
    }
    __syncthreads();
    // v = u @ Wv + bv  (WvT row contiguous)
    if (tid < Dd) {
        ull a6[6];
#pragma unroll
        for (int j = 0; j < 6; j++) a6[j] = 0ull;
        const float4* w4 = (const float4*)(g_WvT + tid * Dd);
#pragma unroll 4
        for (int c = 0; c < 48; c++) {
            float4 w = __ldg(&w4[c]);
            fma12(a6, &uT[(4 * c + 0) * KP], pk2(w.x));
            fma12(a6, &uT[(4 * c + 1) * KP], pk2(w.y));
            fma12(a6, &uT[(4 * c + 2) * KP], pk2(w.z));
            fma12(a6, &uT[(4 * c + 3) * KP], pk2(w.w));
        }
        float bvv = bv[tid];
#pragma unroll
        for (int j = 0; j < 6; j++) {
            float2 f = up2(a6[j]);
            if (2 * j < Kk) vT[tid * KP + 2 * j] = f.x + bvv;
            if (2 * j + 1 < Kk) vT[tid * KP + 2 * j + 1] = f.y + bvv;
        }
        vT[tid * KP + 11] = 0.f;
    }
    __syncthreads();
    // gates: j-th columns, weights rows contiguous in original layout
    int g = tid / 96, tl = tid - g * 96, t = hh * 96 + tl;
    int j = g * Dd + t;
    ull ax6[6], ah6[6];
#pragma unroll
    for (int jj = 0; jj < 6; jj++) { ax6[jj] = 0ull; ah6[jj] = 0ull; }
    const float4* wi4 = (const float4*)(Wih + j * Dd);
    const float4* wh4 = (const float4*)(Whh + j * Dd);
#pragma unroll 4
    for (int c = 0; c < 48; c++) {
        float4 wi = __ldg(&wi4[c]);
        float4 wh = __ldg(&wh4[c]);
        fma12(ax6, &vT[(4 * c + 0) * KP], pk2(wi.x));
        fma12(ax6, &vT[(4 * c + 1) * KP], pk2(wi.y));
        fma12(ax6, &vT[(4 * c + 2) * KP], pk2(wi.z));
        fma12(ax6, &vT[(4 * c + 3) * KP], pk2(wi.w));
        fma12(ah6, &spT[(4 * c + 0) * KP], pk2(wh.x));
        fma12(ah6, &spT[(4 * c + 1) * KP], pk2(wh.y));
        fma12(ah6, &spT[(4 * c + 2) * KP], pk2(wh.z));
        fma12(ah6, &spT[(4 * c + 3) * KP], pk2(wh.w));
    }
    float axf[KP], ahf[KP];
#pragma unroll
    for (int jj = 0; jj < 6; jj++) {
        float2 fx = up2(ax6[jj]), fh = up2(ah6[jj]);
        axf[2 * jj] = fx.x; axf[2 * jj + 1] = fx.y;
        ahf[2 * jj] = fh.x; ahf[2 * jj + 1] = fh.y;
    }
    float bi = bih[j], bh = bhh[j];
    if (g == 0) {
#pragma unroll
        for (int r = 0; r < Kk; r++) P0[tl * KP + r] = axf[r] + ahf[r] + bi + bh;
    } else if (g == 1) {
#pragma unroll
        for (int r = 0; r < Kk; r++) P1[tl * KP + r] = axf[r] + ahf[r] + bi + bh;
    } else {
#pragma unroll
        for (int r = 0; r < Kk; r++) { PXn[tl * KP + r] = axf[r] + bi; PHn[tl * KP + r] = ahf[r] + bh; }
    }
    __syncthreads();
    for (int i = tid; i < Kk * 96; i += 288) {
        int r = i / 96, tl2 = i - r * 96, tg = hh * 96 + tl2;
        float rg = 1.0f / (1.0f + __expf(-P0[tl2 * KP + r]));
        float zg = 1.0f / (1.0f + __expf(-P1[tl2 * KP + r]));
        float ng = tanhf(fmaf(rg, PHn[tl2 * KP + r], PXn[tl2 * KP + r]));
        float hp = spT[tg * KP + r];
        g_h[(b * Kk + r) * Dd + tg] = (1.0f - zg) * ng + zg * hp;
    }
}

// ---------------- LN + MLP + residual ----------------
__global__ __launch_bounds__(192) void k_mlp(const float* __restrict__ lnw,
                                             const float* __restrict__ lnb,
                                             const float* __restrict__ b1,
                                             const float* __restrict__ b2,
                                             float* __restrict__ slots_out, int last) {
    __shared__ float hT[Dd * KP];
    __shared__ float m1T[HIDn * KP];
    int b = blockIdx.x, t = threadIdx.x, wid = t >> 5, lane = t & 31;
    hT[t * KP + 11] = 0.f;
    if (t < HIDn) m1T[t * KP + 11] = 0.f;
    for (int r = wid; r < Kk; r += 6) {
        float v[6], s = 0.f;
#pragma unroll
        for (int i = 0; i < 6; i++) { v[i] = g_h[(b * Kk + r) * Dd + lane + 32 * i]; s += v[i]; }
#pragma unroll
        for (int o = 16; o; o >>= 1) s += __shfl_xor_sync(~0u, s, o);
        float mu = s * (1.0f / Dd), q = 0.f;
#pragma unroll
        for (int i = 0; i < 6; i++) { float d = v[i] - mu; q += d * d; }
#pragma unroll
        for (int o = 16; o; o >>= 1) q += __shfl_xor_sync(~0u, q, o);
        float rstd = rsqrtf(q * (1.0f / Dd) + LN_EPSF);
#pragma unroll
        for (int i = 0; i < 6; i++) {
            int d = lane + 32 * i;
            hT[d * KP + r] = (v[i] - mu) * rstd * lnw[d] + lnb[d];
        }
    }
    __syncthreads();
    if (t < HIDn) {
        ull a6[6];
#pragma unroll
        for (int j = 0; j < 6; j++) a6[j] = 0ull;
        const float4* w4 = (const float4*)(g_W1T + t * Dd);
#pragma unroll 4
        for (int c = 0; c < 48; c++) {
            float4 w = __ldg(&w4[c]);
            fma12(a6, &hT[(4 * c + 0) * KP], pk2(w.x));
            fma12(a6, &hT[(4 * c + 1) * KP], pk2(w.y));
            fma12(a6, &hT[(4 * c + 2) * KP], pk2(w.z));
            fma12(a6, &hT[(4 * c + 3) * KP], pk2(w.w));
        }
        float b1v = b1[t];
#pragma unroll
        for (int j = 0; j < 6; j++) {
            float2 f = up2(a6[j]);
            if (2 * j < Kk) m1T[t * KP + 2 * j] = fmaxf(f.x + b1v, 0.0f);
            if (2 * j + 1 < Kk) m1T[t * KP + 2 * j + 1] = fmaxf(f.y + b1v, 0.0f);
        }
    }
    __syncthreads();
    ull a6[6];
#pragma unroll
    for (int j = 0; j < 6; j++) a6[j] = 0ull;
    {
        const float4* w4 = (const float4*)(g_W2T + t * HIDn);
#pragma unroll 4
        for (int c = 0; c < 32; c++) {
            float4 w = __ldg(&w4[c]);
            fma12(a6, &m1T[(4 * c + 0) * KP], pk2(w.x));
            fma12(a6, &m1T[(4 * c + 1) * KP], pk2(w.y));
            fma12(a6, &m1T[(4 * c + 2) * KP], pk2(w.z));
            fma12(a6, &m1T[(4 * c + 3) * KP], pk2(w.w));
        }
    }
    float acc[Kk];
#pragma unroll
    for (int j = 0; j < 6; j++) {
        float2 f = up2(a6[j]);
        if (2 * j < Kk) acc[2 * j] = f.x;
        if (2 * j + 1 < Kk) acc[2 * j + 1] = f.y;
    }
    float b2v = b2[t];
#pragma unroll
    for (int r = 0; r < Kk; r++) {
        float o = g_h[(b * Kk + r) * Dd + t] + acc[r] + b2v;
        g_slots[(b * Kk + r) * Dd + t] = o;
        if (last) slots_out[(b * Kk + r) * Dd + t] = o;
    }
}

extern "C" void kernel_launch(void* const* d_in, const int* in_sizes, int n_in,
                              void* d_out, int out_size) {
    const float* inputs = (const float*)d_in[0];
    const float* noise = (const float*)d_in[1];
    const float* smu = (const float*)d_in[2];
    const float* ssig = (const float*)d_in[3];
    const float* ln_in_w = (const float*)d_in[4];
    const float* ln_in_b = (const float*)d_in[5];
    const float* ln_sl_w = (const float*)d_in[6];
    const float* ln_sl_b = (const float*)d_in[7];
    const float* ln_ml_w = (const float*)d_in[8];
    const float* ln_ml_b = (const float*)d_in[9];
    const float* Wq = (const float*)d_in[10];
    const float* bq = (const float*)d_in[11];
    const float* Wk = (const float*)d_in[12];
    const float* bk = (const float*)d_in[13];
    const float* Wv = (const float*)d_in[14];
    const float* bv = (const float*)d_in[15];
    const float* Wih = (const float*)d_in[16];
    const float* Whh = (const float*)d_in[17];
    const float* bih = (const float*)d_in[18];
    const float* bhh = (const float*)d_in[19];
    const float* W1 = (const float*)d_in[20];
    const float* b1 = (const float*)d_in[21];
    const float* W2 = (const float*)d_in[22];
    const float* b2 = (const float*)d_in[23];

    float* out = (float*)d_out;
    float* slots_out = out;
    float* attn_out = out + Bn * Kk * Dd;

    const int ATTN_SMEM = (Tt * XST + Kk * Dd) * 4;  // 108,800 bytes
    static bool attr_set = false;
    if (!attr_set) {
        cudaFuncSetAttribute(k_attn, cudaFuncAttributeMaxDynamicSharedMemorySize, ATTN_SMEM);
        attr_set = true;
    }

    k_init<<<384, 256>>>(noise, smu, ssig, Wq, Wv, W1, W2);
    for (int it = 0; it < 3; it++) {
        int last = (it == 2) ? 1 : 0;
        k_pre<<<Bn, 192>>>(ln_sl_w, ln_sl_b, bq, Wk, bk, ln_in_w, ln_in_b);
        k_attn<<<dim3(Nn / Tt, Bn), 128, ATTN_SMEM>>>(inputs, attn_out, last);
        k_gru<<<dim3(2, Bn), 288>>>(bv, Wih, Whh, bih, bhh, ln_in_w, ln_in_b);
        k_mlp<<<Bn, 192>>>(ln_ml_w, ln_ml_b, b1, b2, slots_out, last);
    }
}